// round 2
// baseline (speedup 1.0000x reference)
#include <cuda_runtime.h>
#include <cstdint>
#include <cstddef>

// Problem constants
#define Bm   64     // batch (GEMM M)
#define Sk   720    // seq len (GEMM K)
#define Cc   321    // channels
#define Pp   336    // pred len (GEMM N)
#define WIN  25
#define HALO 12

// Tiling
#define NT   112    // N per block (336 = 3*112)
#define KT   48     // K tile (720 = 15*48)
#define KEXT (KT + 2*HALO)   // 72: extended K tile for smoothing halo

// smem leading dims (padded for bank conflicts / alignment)
#define SA_LD 68    // A tile [KT][SA_LD], 68 keeps float4 alignment (mult of 4)
#define SW_LD 73    // W ext tiles [NT][SW_LD], odd stride -> conflict-free column walks
#define SB_LD 116   // Beff tile [KT][SB_LD]

#define SMEM_FLOATS (KT*SA_LD + 2*NT*SW_LD + KT*SB_LD)
#define SMEM_BYTES  (SMEM_FLOATS * 4)

// Scratch: x transposed to [c][b][s] (59.2 MB), static device array (no allocs).
__device__ float g_xT[(size_t)Cc * Bm * Sk];

// ---------------------------------------------------------------------------
// Kernel 1: transpose x [b][s][c] -> g_xT [c][b][s], coalesced both sides.
// ---------------------------------------------------------------------------
__global__ void transpose_kernel(const float* __restrict__ x) {
    __shared__ float tile[32][33];
    int b  = blockIdx.z;
    int c0 = blockIdx.x * 32;
    int s0 = blockIdx.y * 32;
    int tx = threadIdx.x, ty = threadIdx.y;

    #pragma unroll
    for (int i = 0; i < 4; i++) {
        int s = s0 + ty + 8*i;
        int c = c0 + tx;
        if (s < Sk && c < Cc)
            tile[ty + 8*i][tx] = x[((size_t)b * Sk + s) * Cc + c];
    }
    __syncthreads();
    #pragma unroll
    for (int i = 0; i < 4; i++) {
        int c = c0 + ty + 8*i;
        int s = s0 + tx;
        if (c < Cc && s < Sk)
            g_xT[((size_t)c * Bm + b) * Sk + s] = tile[tx][ty + 8*i];
    }
}

// ---------------------------------------------------------------------------
// Kernel 2: folded GEMM.
//   out[b,c,p] = sum_s xT[c][b][s] * W_eff[c][p][s] + b_res[c,p] + b_trend[c,p]
//   W_eff[p,s] = W_res[p,s] + (1/25) * sum_{t in [s-12,s+12] ∩ [0,720)} (W_trend - W_res)[p,t]
// Built per K-tile in shared memory with a sliding-window sum.
// Block: 256 threads = 16(m) x 16(n); micro-tile 4m x 7n, m packed in pairs
// for fma.rn.f32x2 (full-rate fp32 on sm_103a; 3-reg FFMA is half rate).
// ---------------------------------------------------------------------------
__global__ __launch_bounds__(256, 2) void dlinear_gemm(
    const float* __restrict__ Wres, const float* __restrict__ bres,
    const float* __restrict__ Wtrd, const float* __restrict__ btrd,
    float* __restrict__ out)
{
    extern __shared__ float smem[];
    float* sA  = smem;                      // [KT][SA_LD]   x^T tile, [k][m]
    float* sWr = sA  + KT * SA_LD;          // [NT][SW_LD]   W_res extended tile
    float* sDf = sWr + NT * SW_LD;          // [NT][SW_LD]   (W_trend - W_res) extended
    float* sBe = sDf + NT * SW_LD;          // [KT][SB_LD]   W_eff tile, [k][n]

    const int c   = blockIdx.y;
    const int n0  = blockIdx.x * NT;
    const int tid = threadIdx.x;
    const int tm  = tid >> 4;   // 0..15 -> m base = 4*tm
    const int tn  = tid & 15;   // 0..15 -> n base = 7*tn

    const float* xT = g_xT + (size_t)c * Bm * Sk;
    const float* wr = Wres + ((size_t)c * Pp + n0) * Sk;
    const float* wt = Wtrd + ((size_t)c * Pp + n0) * Sk;

    // accumulators: acc[i][j] = packed {m = 4tm+2i, 4tm+2i+1} x {n = 7tn+j}
    unsigned long long acc[2][7];
    #pragma unroll
    for (int i = 0; i < 2; i++)
        #pragma unroll
        for (int j = 0; j < 7; j++) acc[i][j] = 0ULL;

    for (int k0 = 0; k0 < Sk; k0 += KT) {
        // ---- load A tile: KT*Bm = 3072 floats, 12 per thread, coalesced in k ----
        #pragma unroll
        for (int j = 0; j < (KT * Bm) / 256; j++) {
            int idx = tid + 256 * j;
            int m = idx / KT, k = idx % KT;
            sA[k * SA_LD + m] = xT[(size_t)m * Sk + k0 + k];
        }
        // ---- load extended W tiles (zero-padded outside [0,720)) ----
        #pragma unroll
        for (int j = 0; j < 32; j++) {
            int idx = tid + 256 * j;
            if (idx < NT * KEXT) {
                int n = idx / KEXT, t = idx % KEXT;
                int s = k0 - HALO + t;
                float a = 0.f, d = 0.f;
                if (s >= 0 && s < Sk) {
                    a = wr[(size_t)n * Sk + s];
                    d = wt[(size_t)n * Sk + s] - a;
                }
                sWr[n * SW_LD + t] = a;
                sDf[n * SW_LD + t] = d;
            }
        }
        __syncthreads();

        // ---- build W_eff tile via sliding 25-tap window ----
        // thread -> (n, 24-wide k chunk); window for local k is sDf[n][k..k+24]
        if (tid < 2 * NT) {
            int n  = tid % NT;
            int kb = (tid / NT) * 24;
            const float* dfn = sDf + n * SW_LD;
            float ws = 0.f;
            #pragma unroll
            for (int t = 0; t < WIN; t++) ws += dfn[kb + t];
            #pragma unroll
            for (int i = 0; i < 24; i++) {
                int k = kb + i;
                sBe[k * SB_LD + n] = sWr[n * SW_LD + k + HALO] + ws * (1.0f / 25.0f);
                if (i < 23) ws += dfn[k + WIN] - dfn[k];
            }
        }
        __syncthreads();

        // ---- main FMA loop (f32x2 packed) ----
        #pragma unroll 4
        for (int k = 0; k < KT; k++) {
            float4 av = *(const float4*)(sA + k * SA_LD + tm * 4);
            unsigned long long a01, a23;
            asm("mov.b64 %0, {%1, %2};" : "=l"(a01) : "f"(av.x), "f"(av.y));
            asm("mov.b64 %0, {%1, %2};" : "=l"(a23) : "f"(av.z), "f"(av.w));
            const float* ber = sBe + k * SB_LD + tn * 7;
            #pragma unroll
            for (int j = 0; j < 7; j++) {
                float bf = ber[j];
                unsigned long long bb;
                asm("mov.b64 %0, {%1, %1};" : "=l"(bb) : "f"(bf));
                asm("fma.rn.f32x2 %0, %1, %2, %0;" : "+l"(acc[0][j]) : "l"(a01), "l"(bb));
                asm("fma.rn.f32x2 %0, %1, %2, %0;" : "+l"(acc[1][j]) : "l"(a23), "l"(bb));
            }
        }
        __syncthreads();
    }

    // ---- epilogue: add biases, write out[b][c][p] ----
    #pragma unroll
    for (int j = 0; j < 7; j++) {
        int p = n0 + tn * 7 + j;
        float bias = bres[(size_t)c * Pp + p] + btrd[(size_t)c * Pp + p];
        #pragma unroll
        for (int i = 0; i < 2; i++) {
            float lo, hi;
            asm("mov.b64 {%0, %1}, %2;" : "=f"(lo), "=f"(hi) : "l"(acc[i][j]));
            int m = tm * 4 + i * 2;
            out[((size_t)m       * Cc + c) * Pp + p] = lo + bias;
            out[((size_t)(m + 1) * Cc + c) * Pp + p] = hi + bias;
        }
    }
}

// ---------------------------------------------------------------------------
extern "C" void kernel_launch(void* const* d_in, const int* in_sizes, int n_in,
                              void* d_out, int out_size) {
    (void)in_sizes; (void)n_in; (void)out_size;
    const float* x    = (const float*)d_in[0];
    const float* Wres = (const float*)d_in[1];
    const float* bres = (const float*)d_in[2];
    const float* Wtrd = (const float*)d_in[3];
    const float* btrd = (const float*)d_in[4];
    float* out = (float*)d_out;

    dim3 tgrid((Cc + 31) / 32, (Sk + 31) / 32, Bm);
    transpose_kernel<<<tgrid, dim3(32, 8)>>>(x);

    cudaFuncSetAttribute(dlinear_gemm,
                         cudaFuncAttributeMaxDynamicSharedMemorySize, SMEM_BYTES);
    dlinear_gemm<<<dim3(Pp / NT, Cc), 256, SMEM_BYTES>>>(Wres, bres, Wtrd, btrd, out);
}